// round 14
// baseline (speedup 1.0000x reference)
#include <cuda_runtime.h>
#include <cuda_fp16.h>
#include <cstdint>

// Single-term fp16 GEMM over compacted valid tokens; surplus GEMM CTAs
// zero the invalid output rows. 512 threads / 16 warps, 32x64 warp tiles,
// register-level kf software pipeline (double-buffered fragments).
//
// Problem constants
#define TOKENS       12800
#define K_DIM        1152
#define D_SEM_DIM    768
#define D_PROMPT_DIM 384
#define N_DIM        2048
#define NUM_ITEMS_C  100000

// GEMM tiling
#define BM      128
#define BN      256
#define BK      64
#define NSLAB   (K_DIM / BK)               // 18
#define STAGES  4
#define NTHREADS 512

#define A_BYTES     (BM * BK * 2)          // 16384 (row stride 128 B)
#define B_BYTES     (BN * BK * 2)          // 32768
#define STAGE_BYTES (A_BYTES + B_BYTES)    // 49152
#define SMEM_TOTAL  (STAGES * STAGE_BYTES) // 196608

// fp16 operands: A gathered+compacted, W converted
__device__ __align__(256) __half g_Ah[(size_t)TOKENS * K_DIM];
__device__ __align__(256) __half g_Wh[(size_t)N_DIM * K_DIM];
// compaction state
__device__ int g_count;          // # valid tokens
__device__ int g_icount;         // # invalid tokens
__device__ int g_slot[TOKENS];   // orig token -> compacted slot (-1 invalid)
__device__ int g_c2o[TOKENS];    // compacted slot -> orig token
__device__ int g_inv[TOKENS];    // invalid list -> orig token

// ---------------- helpers ----------------
__device__ __forceinline__ uint32_t smem_u32_of(const void* p) {
    uint32_t a;
    asm("{ .reg .u64 t; cvta.to.shared.u64 t, %1; cvt.u32.u64 %0, t; }" : "=r"(a) : "l"(p));
    return a;
}
__device__ __forceinline__ void cp16(uint32_t dst, const void* src) {
    asm volatile("cp.async.cg.shared.global [%0], [%1], 16;" :: "r"(dst), "l"(src) : "memory");
}
__device__ __forceinline__ void ldsm4(uint32_t* r, uint32_t addr) {
    asm volatile("ldmatrix.sync.aligned.m8n8.x4.shared.b16 {%0,%1,%2,%3}, [%4];"
                 : "=r"(r[0]), "=r"(r[1]), "=r"(r[2]), "=r"(r[3]) : "r"(addr));
}
__device__ __forceinline__ void mma16816(float* d, const uint32_t* a, const uint32_t* b) {
    asm volatile(
        "mma.sync.aligned.m16n8k16.row.col.f32.f16.f16.f32 "
        "{%0,%1,%2,%3}, {%4,%5,%6,%7}, {%8,%9}, {%0,%1,%2,%3};"
        : "+f"(d[0]), "+f"(d[1]), "+f"(d[2]), "+f"(d[3])
        : "r"(a[0]), "r"(a[1]), "r"(a[2]), "r"(a[3]), "r"(b[0]), "r"(b[1]));
}
// 128B-row swizzle: chunk' = c ^ (row & 7)
__device__ __forceinline__ uint32_t chswz(int row, int c) {
    return (uint32_t)(row * 128 + ((c ^ (row & 7)) << 4));
}

// load one K-slab (A 128x64, W 256x64 fp16) into a pipeline stage
__device__ __forceinline__ void load_slab(uint32_t smem_u32, int stage, int s,
                                          int i0, int n0, int tid) {
    const int kk = s * BK;
    const uint32_t stA = smem_u32 + stage * STAGE_BYTES;
    const uint32_t stB = stA + A_BYTES;
    #pragma unroll
    for (int i = 0; i < 2; i++) {                        // A: 1024 chunks of 16B
        int j = tid + NTHREADS * i, r = j >> 3, c = j & 7;
        cp16(stA + chswz(r, c), g_Ah + (size_t)(i0 + r) * K_DIM + kk + c * 8);
    }
    #pragma unroll
    for (int i = 0; i < 4; i++) {                        // W: 2048 chunks
        int j = tid + NTHREADS * i, r = j >> 3, c = j & 7;
        cp16(stB + chswz(r, c), g_Wh + (size_t)(n0 + r) * K_DIM + kk + c * 8);
    }
    asm volatile("cp.async.commit_group;" ::: "memory");
}

// fragment load for one kf step: a = 2 LDSM (32 rows), b = 4 LDSM (64 cols)
__device__ __forceinline__ void load_frags(uint32_t stA, uint32_t stB, int kf,
                                           int wm, int wn, int lid,
                                           uint32_t a[2][4], uint32_t b[4][4]) {
    #pragma unroll
    for (int p = 0; p < 2; p++) {
        int row = wm * 32 + p * 16 + (lid & 7) + ((lid >> 3) & 1) * 8;
        int ch  = 2 * kf + (lid >> 4);
        ldsm4(a[p], stA + chswz(row, ch));
    }
    #pragma unroll
    for (int p = 0; p < 4; p++) {
        int row = wn * 64 + p * 16 + (lid & 7) + (lid >> 4) * 8;
        int ch  = 2 * kf + ((lid >> 3) & 1);
        ldsm4(b[p], stB + chswz(row, ch));
    }
}

// ---------------- GEMM kernel (+ invalid-row zeroing on surplus tiles) ----
__global__ __launch_bounds__(NTHREADS, 1)
void gemm_kernel(float* __restrict__ out)
{
    const int n_valid  = g_count;
    const int nv_tiles = (n_valid + BM - 1) / BM;
    const int tid = threadIdx.x;
    const int lid = tid & 31;
    const int wid = tid >> 5;
    const int n0  = blockIdx.x * BN;

    if ((int)blockIdx.y >= nv_tiles) {
        // surplus tile: zero invalid original rows for this BN column slice.
        const int yr = blockIdx.y - nv_tiles;
        const int n_invalid = TOKENS - n_valid;
        const float4 z = make_float4(0.f, 0.f, 0.f, 0.f);
        #pragma unroll
        for (int j = wid; j < BM; j += 16) {        // one warp per row
            int inv = yr * BM + j;
            if (inv < n_invalid) {
                float* p = out + (size_t)g_inv[inv] * N_DIM + n0 + lid * 8;
                *(float4*)p       = z;
                *(float4*)(p + 4) = z;
            }
        }
        return;
    }

    const int i0 = blockIdx.y * BM;      // compacted-row tile start
    extern __shared__ char smem[];
    const uint32_t smem_u32 = smem_u32_of(smem);
    const int wm  = wid >> 2;            // 0..3 (32-row slab)
    const int wn  = wid & 3;             // 0..3 (64-col slab)

    __shared__ int s_orig[BM];
    if (tid < BM)
        s_orig[tid] = (i0 + tid < n_valid) ? g_c2o[i0 + tid] : -1;

    float acc[2][8][4];
    #pragma unroll
    for (int mf = 0; mf < 2; mf++)
        #pragma unroll
        for (int nf = 0; nf < 8; nf++)
            #pragma unroll
            for (int q = 0; q < 4; q++) acc[mf][nf][q] = 0.f;

    // prologue: stages 0..2
    load_slab(smem_u32, 0, 0, i0, n0, tid);
    load_slab(smem_u32, 1, 1, i0, n0, tid);
    load_slab(smem_u32, 2, 2, i0, n0, tid);

    uint32_t afr[2][2][4], bfr[2][4][4];   // double-buffered fragments

    for (int s = 0; s < NSLAB; ++s) {
        if (s < NSLAB - 2)      asm volatile("cp.async.wait_group 2;" ::: "memory");
        else if (s < NSLAB - 1) asm volatile("cp.async.wait_group 1;" ::: "memory");
        else                    asm volatile("cp.async.wait_group 0;" ::: "memory");
        __syncthreads();

        if (s + 3 < NSLAB)
            load_slab(smem_u32, (s + 3) & 3, s + 3, i0, n0, tid);

        const uint32_t stA = smem_u32 + (s & 3) * STAGE_BYTES;
        const uint32_t stB = stA + A_BYTES;

        // kf register pipeline: prefetch kf+1 while computing kf
        load_frags(stA, stB, 0, wm, wn, lid, afr[0], bfr[0]);
        #pragma unroll
        for (int kf = 0; kf < 4; kf++) {
            const int cur = kf & 1;
            if (kf < 3)
                load_frags(stA, stB, kf + 1, wm, wn, lid, afr[cur ^ 1], bfr[cur ^ 1]);
            #pragma unroll
            for (int mf = 0; mf < 2; mf++)
                #pragma unroll
                for (int nf = 0; nf < 8; nf++)
                    mma16816(acc[mf][nf], afr[cur][mf], &bfr[cur][nf >> 1][(nf & 1) * 2]);
        }
    }
    __syncthreads();

    // epilogue: scatter compacted rows back to original token rows
    const int g = lid >> 2, t = lid & 3;
    #pragma unroll
    for (int mf = 0; mf < 2; mf++) {
        const int r0 = wm * 32 + mf * 16 + g;
        const int o0 = s_orig[r0];
        const int o1 = s_orig[r0 + 8];
        #pragma unroll
        for (int nf = 0; nf < 8; nf++) {
            const int col = n0 + wn * 64 + nf * 8 + t * 2;
            if (o0 >= 0)
                *(float2*)&out[(size_t)o0 * N_DIM + col] =
                    make_float2(acc[mf][nf][0], acc[mf][nf][1]);
            if (o1 >= 0)
                *(float2*)&out[(size_t)o1 * N_DIM + col] =
                    make_float2(acc[mf][nf][2], acc[mf][nf][3]);
        }
    }
}

// ---------------- pre-pass kernels ----------------
__device__ __forceinline__ void cvt4_store(float4 x, __half* ph) {
    union { __half b[4]; uint2 u; } uh;
    uh.b[0] = __float2half(x.x); uh.b[1] = __float2half(x.y);
    uh.b[2] = __float2half(x.z); uh.b[3] = __float2half(x.w);
    *(uint2*)ph = uh.u;
}

__global__ void convert_w_kernel(const float* __restrict__ W) {
    if (blockIdx.x == 0 && threadIdx.x == 0) { g_count = 0; g_icount = 0; }
    const int n = blockIdx.x;
    const int k = threadIdx.x * 4;              // 288 threads cover K=1152
    const size_t o = (size_t)n * K_DIM + k;
    cvt4_store(*(const float4*)&W[o], g_Wh + o);
}

// assign compacted slots + invalid list + write amask / tok_item_ids
__global__ void compact_kernel(const int* __restrict__ ids, float* __restrict__ out) {
    int i = blockIdx.x * 256 + threadIdx.x;
    if (i >= TOKENS) return;
    int id = ids[i];
    bool valid = (id >= 0 && id < NUM_ITEMS_C);
    const size_t base = (size_t)TOKENS * N_DIM;
    out[base + i]          = valid ? 1.0f : 0.0f;
    out[base + TOKENS + i] = valid ? (float)id : -1.0f;
    if (valid) {
        int s = atomicAdd(&g_count, 1);
        g_slot[i] = s;
        g_c2o[s] = i;
    } else {
        g_slot[i] = -1;
        int s = atomicAdd(&g_icount, 1);
        g_inv[s] = i;
    }
}

// gather valid tokens into compacted rows, fp16
__global__ void gather_kernel(const int* __restrict__ ids,
                              const float* __restrict__ E,
                              const float* __restrict__ V) {
    const int i = blockIdx.x;
    const int slot = g_slot[i];
    if (slot < 0) return;
    const int k = threadIdx.x * 4;
    const int id = ids[i];
    float4 x = (k < D_SEM_DIM)
        ? *(const float4*)&E[(size_t)id * D_SEM_DIM + k]
        : *(const float4*)&V[(size_t)id * D_PROMPT_DIM + (k - D_SEM_DIM)];
    cvt4_store(x, g_Ah + (size_t)slot * K_DIM + k);
}

extern "C" void kernel_launch(void* const* d_in, const int* in_sizes, int n_in,
                              void* d_out, int out_size)
{
    const int*   ids      = (const int*)  d_in[0];
    const float* E_sem    = (const float*)d_in[2];
    const float* v_prompt = (const float*)d_in[3];
    const float* W        = (const float*)d_in[4];
    float*       out      = (float*)d_out;

    static bool attr_set = false;
    if (!attr_set) {
        cudaFuncSetAttribute(gemm_kernel, cudaFuncAttributeMaxDynamicSharedMemorySize, SMEM_TOTAL);
        attr_set = true;
    }

    convert_w_kernel<<<N_DIM, 288>>>(W);                         // also resets counters
    compact_kernel<<<(TOKENS + 255) / 256, 256>>>(ids, out);     // slots + inv list + amask/tok
    gather_kernel<<<TOKENS, 288>>>(ids, E_sem, v_prompt);        // compacted fp16 A
    dim3 grid(N_DIM / BN, TOKENS / BM + 1);                      // (8, 101): valid tiles GEMM,
    gemm_kernel<<<grid, NTHREADS, SMEM_TOTAL>>>(out);            // surplus tiles zero invalid rows
}

// round 15
// speedup vs baseline: 1.0920x; 1.0920x over previous
#include <cuda_runtime.h>
#include <cuda_fp16.h>
#include <cstdint>

// Single-term fp16 GEMM over compacted valid tokens; surplus GEMM CTAs
// zero the invalid output rows. 256 threads / 8 warps, 32x64 warp tiles,
// BN=128, 3-stage pipeline, 2 CTAs per SM for barrier overlap.
//
// Problem constants
#define TOKENS       12800
#define K_DIM        1152
#define D_SEM_DIM    768
#define D_PROMPT_DIM 384
#define N_DIM        2048
#define NUM_ITEMS_C  100000

// GEMM tiling
#define BM      128
#define BN      128
#define BK      64
#define NSLAB   (K_DIM / BK)               // 18
#define STAGES  3
#define NTHREADS 256

#define A_BYTES     (BM * BK * 2)          // 16384 (row stride 128 B)
#define B_BYTES     (BN * BK * 2)          // 16384
#define STAGE_BYTES (A_BYTES + B_BYTES)    // 32768
#define SMEM_TOTAL  (STAGES * STAGE_BYTES) // 98304 -> 2 CTAs/SM

// fp16 operands: A gathered+compacted, W converted
__device__ __align__(256) __half g_Ah[(size_t)TOKENS * K_DIM];
__device__ __align__(256) __half g_Wh[(size_t)N_DIM * K_DIM];
// compaction state
__device__ int g_count;          // # valid tokens
__device__ int g_icount;         // # invalid tokens
__device__ int g_slot[TOKENS];   // orig token -> compacted slot (-1 invalid)
__device__ int g_c2o[TOKENS];    // compacted slot -> orig token
__device__ int g_inv[TOKENS];    // invalid list -> orig token

// ---------------- helpers ----------------
__device__ __forceinline__ uint32_t smem_u32_of(const void* p) {
    uint32_t a;
    asm("{ .reg .u64 t; cvta.to.shared.u64 t, %1; cvt.u32.u64 %0, t; }" : "=r"(a) : "l"(p));
    return a;
}
__device__ __forceinline__ void cp16(uint32_t dst, const void* src) {
    asm volatile("cp.async.cg.shared.global [%0], [%1], 16;" :: "r"(dst), "l"(src) : "memory");
}
__device__ __forceinline__ void ldsm4(uint32_t* r, uint32_t addr) {
    asm volatile("ldmatrix.sync.aligned.m8n8.x4.shared.b16 {%0,%1,%2,%3}, [%4];"
                 : "=r"(r[0]), "=r"(r[1]), "=r"(r[2]), "=r"(r[3]) : "r"(addr));
}
__device__ __forceinline__ void mma16816(float* d, const uint32_t* a, const uint32_t* b) {
    asm volatile(
        "mma.sync.aligned.m16n8k16.row.col.f32.f16.f16.f32 "
        "{%0,%1,%2,%3}, {%4,%5,%6,%7}, {%8,%9}, {%0,%1,%2,%3};"
        : "+f"(d[0]), "+f"(d[1]), "+f"(d[2]), "+f"(d[3])
        : "r"(a[0]), "r"(a[1]), "r"(a[2]), "r"(a[3]), "r"(b[0]), "r"(b[1]));
}
// 128B-row swizzle: chunk' = c ^ (row & 7)
__device__ __forceinline__ uint32_t chswz(int row, int c) {
    return (uint32_t)(row * 128 + ((c ^ (row & 7)) << 4));
}

// load one K-slab (A 128x64, W 128x64 fp16) into a pipeline stage
__device__ __forceinline__ void load_slab(uint32_t smem_u32, int stage, int s,
                                          int i0, int n0, int tid) {
    const int kk = s * BK;
    const uint32_t stA = smem_u32 + stage * STAGE_BYTES;
    const uint32_t stB = stA + A_BYTES;
    #pragma unroll
    for (int i = 0; i < 4; i++) {                        // A: 1024 chunks of 16B
        int j = tid + NTHREADS * i, r = j >> 3, c = j & 7;
        cp16(stA + chswz(r, c), g_Ah + (size_t)(i0 + r) * K_DIM + kk + c * 8);
    }
    #pragma unroll
    for (int i = 0; i < 4; i++) {                        // W: 1024 chunks
        int j = tid + NTHREADS * i, r = j >> 3, c = j & 7;
        cp16(stB + chswz(r, c), g_Wh + (size_t)(n0 + r) * K_DIM + kk + c * 8);
    }
    asm volatile("cp.async.commit_group;" ::: "memory");
}

// ---------------- GEMM kernel (+ invalid-row zeroing on surplus tiles) ----
__global__ __launch_bounds__(NTHREADS, 2)
void gemm_kernel(float* __restrict__ out)
{
    const int n_valid  = g_count;
    const int nv_tiles = (n_valid + BM - 1) / BM;
    const int tid = threadIdx.x;
    const int lid = tid & 31;
    const int wid = tid >> 5;
    const int n0  = blockIdx.x * BN;

    if ((int)blockIdx.y >= nv_tiles) {
        // surplus tile: zero invalid original rows for this BN column slice.
        const int yr = blockIdx.y - nv_tiles;
        const int n_invalid = TOKENS - n_valid;
        const float4 z = make_float4(0.f, 0.f, 0.f, 0.f);
        #pragma unroll
        for (int j = wid; j < BM; j += 8) {         // one warp per row
            int inv = yr * BM + j;
            if (inv < n_invalid) {
                float* p = out + (size_t)g_inv[inv] * N_DIM + n0 + lid * 4;
                *(float4*)p = z;                     // 32 lanes x 4 = 128 cols
            }
        }
        return;
    }

    const int i0 = blockIdx.y * BM;      // compacted-row tile start
    extern __shared__ char smem[];
    const uint32_t smem_u32 = smem_u32_of(smem);
    const int wm  = wid >> 1;            // 0..3 (32-row slab)
    const int wn  = wid & 1;             // 0..1 (64-col slab)

    __shared__ int s_orig[BM];
    if (tid < BM)
        s_orig[tid] = (i0 + tid < n_valid) ? g_c2o[i0 + tid] : -1;

    float acc[2][8][4];
    #pragma unroll
    for (int mf = 0; mf < 2; mf++)
        #pragma unroll
        for (int nf = 0; nf < 8; nf++)
            #pragma unroll
            for (int q = 0; q < 4; q++) acc[mf][nf][q] = 0.f;

    // prologue: stages 0..1
    load_slab(smem_u32, 0, 0, i0, n0, tid);
    load_slab(smem_u32, 1, 1, i0, n0, tid);

    int stage = 0;
    for (int s = 0; s < NSLAB; ++s) {
        if (s + 2 < NSLAB)
            load_slab(smem_u32, (stage + 2) % 3, s + 2, i0, n0, tid);
        // allow the newer in-flight groups to remain pending
        if (s + 2 < NSLAB)      asm volatile("cp.async.wait_group 2;" ::: "memory");
        else if (s + 1 < NSLAB) asm volatile("cp.async.wait_group 1;" ::: "memory");
        else                    asm volatile("cp.async.wait_group 0;" ::: "memory");
        __syncthreads();

        const uint32_t stA = smem_u32 + stage * STAGE_BYTES;
        const uint32_t stB = stA + A_BYTES;

        #pragma unroll
        for (int kf = 0; kf < 4; kf++) {
            uint32_t a[2][4], b[4][4];
            #pragma unroll
            for (int p = 0; p < 2; p++) {
                int row = wm * 32 + p * 16 + (lid & 7) + ((lid >> 3) & 1) * 8;
                int ch  = 2 * kf + (lid >> 4);
                ldsm4(a[p], stA + chswz(row, ch));
            }
            #pragma unroll
            for (int p = 0; p < 4; p++) {
                int row = wn * 64 + p * 16 + (lid & 7) + (lid >> 4) * 8;
                int ch  = 2 * kf + ((lid >> 3) & 1);
                ldsm4(b[p], stB + chswz(row, ch));
            }
            #pragma unroll
            for (int mf = 0; mf < 2; mf++)
                #pragma unroll
                for (int nf = 0; nf < 8; nf++)
                    mma16816(acc[mf][nf], a[mf], &b[nf >> 1][(nf & 1) * 2]);
        }
        __syncthreads();
        stage = (stage + 1) % 3;
    }

    // epilogue: scatter compacted rows back to original token rows
    const int g = lid >> 2, t = lid & 3;
    #pragma unroll
    for (int mf = 0; mf < 2; mf++) {
        const int r0 = wm * 32 + mf * 16 + g;
        const int o0 = s_orig[r0];
        const int o1 = s_orig[r0 + 8];
        #pragma unroll
        for (int nf = 0; nf < 8; nf++) {
            const int col = n0 + wn * 64 + nf * 8 + t * 2;
            if (o0 >= 0)
                *(float2*)&out[(size_t)o0 * N_DIM + col] =
                    make_float2(acc[mf][nf][0], acc[mf][nf][1]);
            if (o1 >= 0)
                *(float2*)&out[(size_t)o1 * N_DIM + col] =
                    make_float2(acc[mf][nf][2], acc[mf][nf][3]);
        }
    }
}

// ---------------- pre-pass kernels ----------------
__device__ __forceinline__ void cvt4_store(float4 x, __half* ph) {
    union { __half b[4]; uint2 u; } uh;
    uh.b[0] = __float2half(x.x); uh.b[1] = __float2half(x.y);
    uh.b[2] = __float2half(x.z); uh.b[3] = __float2half(x.w);
    *(uint2*)ph = uh.u;
}

__global__ void convert_w_kernel(const float* __restrict__ W) {
    if (blockIdx.x == 0 && threadIdx.x == 0) { g_count = 0; g_icount = 0; }
    const int n = blockIdx.x;
    const int k = threadIdx.x * 4;              // 288 threads cover K=1152
    const size_t o = (size_t)n * K_DIM + k;
    cvt4_store(*(const float4*)&W[o], g_Wh + o);
}

// assign compacted slots + invalid list + write amask / tok_item_ids
__global__ void compact_kernel(const int* __restrict__ ids, float* __restrict__ out) {
    int i = blockIdx.x * 256 + threadIdx.x;
    if (i >= TOKENS) return;
    int id = ids[i];
    bool valid = (id >= 0 && id < NUM_ITEMS_C);
    const size_t base = (size_t)TOKENS * N_DIM;
    out[base + i]          = valid ? 1.0f : 0.0f;
    out[base + TOKENS + i] = valid ? (float)id : -1.0f;
    if (valid) {
        int s = atomicAdd(&g_count, 1);
        g_slot[i] = s;
        g_c2o[s] = i;
    } else {
        g_slot[i] = -1;
        int s = atomicAdd(&g_icount, 1);
        g_inv[s] = i;
    }
}

// gather valid tokens into compacted rows, fp16
__global__ void gather_kernel(const int* __restrict__ ids,
                              const float* __restrict__ E,
                              const float* __restrict__ V) {
    const int i = blockIdx.x;
    const int slot = g_slot[i];
    if (slot < 0) return;
    const int k = threadIdx.x * 4;
    const int id = ids[i];
    float4 x = (k < D_SEM_DIM)
        ? *(const float4*)&E[(size_t)id * D_SEM_DIM + k]
        : *(const float4*)&V[(size_t)id * D_PROMPT_DIM + (k - D_SEM_DIM)];
    cvt4_store(x, g_Ah + (size_t)slot * K_DIM + k);
}

extern "C" void kernel_launch(void* const* d_in, const int* in_sizes, int n_in,
                              void* d_out, int out_size)
{
    const int*   ids      = (const int*)  d_in[0];
    const float* E_sem    = (const float*)d_in[2];
    const float* v_prompt = (const float*)d_in[3];
    const float* W        = (const float*)d_in[4];
    float*       out      = (float*)d_out;

    static bool attr_set = false;
    if (!attr_set) {
        cudaFuncSetAttribute(gemm_kernel, cudaFuncAttributeMaxDynamicSharedMemorySize, SMEM_TOTAL);
        attr_set = true;
    }

    convert_w_kernel<<<N_DIM, 288>>>(W);                         // also resets counters
    compact_kernel<<<(TOKENS + 255) / 256, 256>>>(ids, out);     // slots + inv list + amask/tok
    gather_kernel<<<TOKENS, 288>>>(ids, E_sem, v_prompt);        // compacted fp16 A
    dim3 grid(N_DIM / BN, TOKENS / BM + 1);                      // (16, 101)
    gemm_kernel<<<grid, NTHREADS, SMEM_TOTAL>>>(out);            // surplus tiles zero invalid rows
}

// round 16
// speedup vs baseline: 1.1074x; 1.0141x over previous
#include <cuda_runtime.h>
#include <cuda_fp16.h>
#include <cstdint>

// Single-term fp16 GEMM over compacted valid tokens; surplus GEMM CTAs
// zero the invalid output rows. 256 threads / 8 warps, 32x64 warp tiles,
// BN=128, 3-stage pipeline, 2 CTAs per SM, ONE barrier per K-slab.
//
// Problem constants
#define TOKENS       12800
#define K_DIM        1152
#define D_SEM_DIM    768
#define D_PROMPT_DIM 384
#define N_DIM        2048
#define NUM_ITEMS_C  100000

// GEMM tiling
#define BM      128
#define BN      128
#define BK      64
#define NSLAB   (K_DIM / BK)               // 18
#define STAGES  3
#define NTHREADS 256

#define A_BYTES     (BM * BK * 2)          // 16384 (row stride 128 B)
#define B_BYTES     (BN * BK * 2)          // 16384
#define STAGE_BYTES (A_BYTES + B_BYTES)    // 32768
#define SMEM_TOTAL  (STAGES * STAGE_BYTES) // 98304 -> 2 CTAs/SM

// fp16 operands: A gathered+compacted, W converted
__device__ __align__(256) __half g_Ah[(size_t)TOKENS * K_DIM];
__device__ __align__(256) __half g_Wh[(size_t)N_DIM * K_DIM];
// compaction state
__device__ int g_count;          // # valid tokens
__device__ int g_icount;         // # invalid tokens
__device__ int g_slot[TOKENS];   // orig token -> compacted slot (-1 invalid)
__device__ int g_c2o[TOKENS];    // compacted slot -> orig token
__device__ int g_inv[TOKENS];    // invalid list -> orig token

// ---------------- helpers ----------------
__device__ __forceinline__ uint32_t smem_u32_of(const void* p) {
    uint32_t a;
    asm("{ .reg .u64 t; cvta.to.shared.u64 t, %1; cvt.u32.u64 %0, t; }" : "=r"(a) : "l"(p));
    return a;
}
__device__ __forceinline__ void cp16(uint32_t dst, const void* src) {
    asm volatile("cp.async.cg.shared.global [%0], [%1], 16;" :: "r"(dst), "l"(src) : "memory");
}
__device__ __forceinline__ void ldsm4(uint32_t* r, uint32_t addr) {
    asm volatile("ldmatrix.sync.aligned.m8n8.x4.shared.b16 {%0,%1,%2,%3}, [%4];"
                 : "=r"(r[0]), "=r"(r[1]), "=r"(r[2]), "=r"(r[3]) : "r"(addr));
}
__device__ __forceinline__ void mma16816(float* d, const uint32_t* a, const uint32_t* b) {
    asm volatile(
        "mma.sync.aligned.m16n8k16.row.col.f32.f16.f16.f32 "
        "{%0,%1,%2,%3}, {%4,%5,%6,%7}, {%8,%9}, {%0,%1,%2,%3};"
        : "+f"(d[0]), "+f"(d[1]), "+f"(d[2]), "+f"(d[3])
        : "r"(a[0]), "r"(a[1]), "r"(a[2]), "r"(a[3]), "r"(b[0]), "r"(b[1]));
}
// 128B-row swizzle: chunk' = c ^ (row & 7)
__device__ __forceinline__ uint32_t chswz(int row, int c) {
    return (uint32_t)(row * 128 + ((c ^ (row & 7)) << 4));
}

// load one K-slab (A 128x64, W 128x64 fp16) into a pipeline stage
__device__ __forceinline__ void load_slab(uint32_t smem_u32, int stage, int s,
                                          int i0, int n0, int tid) {
    const int kk = s * BK;
    const uint32_t stA = smem_u32 + stage * STAGE_BYTES;
    const uint32_t stB = stA + A_BYTES;
    #pragma unroll
    for (int i = 0; i < 4; i++) {                        // A: 1024 chunks of 16B
        int j = tid + NTHREADS * i, r = j >> 3, c = j & 7;
        cp16(stA + chswz(r, c), g_Ah + (size_t)(i0 + r) * K_DIM + kk + c * 8);
    }
    #pragma unroll
    for (int i = 0; i < 4; i++) {                        // W: 1024 chunks
        int j = tid + NTHREADS * i, r = j >> 3, c = j & 7;
        cp16(stB + chswz(r, c), g_Wh + (size_t)(n0 + r) * K_DIM + kk + c * 8);
    }
    asm volatile("cp.async.commit_group;" ::: "memory");
}

// ---------------- GEMM kernel (+ invalid-row zeroing on surplus tiles) ----
__global__ __launch_bounds__(NTHREADS, 2)
void gemm_kernel(float* __restrict__ out)
{
    const int n_valid  = g_count;
    const int nv_tiles = (n_valid + BM - 1) / BM;
    const int tid = threadIdx.x;
    const int lid = tid & 31;
    const int wid = tid >> 5;
    const int n0  = blockIdx.x * BN;

    if ((int)blockIdx.y >= nv_tiles) {
        // surplus tile: zero invalid original rows for this BN column slice.
        const int yr = blockIdx.y - nv_tiles;
        const int n_invalid = TOKENS - n_valid;
        const float4 z = make_float4(0.f, 0.f, 0.f, 0.f);
        #pragma unroll
        for (int j = wid; j < BM; j += 8) {         // one warp per row
            int inv = yr * BM + j;
            if (inv < n_invalid) {
                float* p = out + (size_t)g_inv[inv] * N_DIM + n0 + lid * 4;
                *(float4*)p = z;                     // 32 lanes x 4 = 128 cols
            }
        }
        return;
    }

    const int i0 = blockIdx.y * BM;      // compacted-row tile start
    extern __shared__ char smem[];
    const uint32_t smem_u32 = smem_u32_of(smem);
    const int wm  = wid >> 1;            // 0..3 (32-row slab)
    const int wn  = wid & 1;             // 0..1 (64-col slab)

    __shared__ int s_orig[BM];
    if (tid < BM)
        s_orig[tid] = (i0 + tid < n_valid) ? g_c2o[i0 + tid] : -1;

    float acc[2][8][4];
    #pragma unroll
    for (int mf = 0; mf < 2; mf++)
        #pragma unroll
        for (int nf = 0; nf < 8; nf++)
            #pragma unroll
            for (int q = 0; q < 4; q++) acc[mf][nf][q] = 0.f;

    // prologue: stages 0..1
    load_slab(smem_u32, 0, 0, i0, n0, tid);
    load_slab(smem_u32, 1, 1, i0, n0, tid);

    int stage = 0;
    for (int s = 0; s < NSLAB; ++s) {
        // ensure group s landed (allow 1 newer pending)
        if (s < NSLAB - 1) asm volatile("cp.async.wait_group 1;" ::: "memory");
        else               asm volatile("cp.async.wait_group 0;" ::: "memory");
        // SINGLE barrier per slab: orders (a) stage-s data visibility and
        // (b) last iteration's reads of stage (s+2)%3 before we overwrite it.
        __syncthreads();

        if (s + 2 < NSLAB) {
            int wstage = stage + 2 >= STAGES ? stage - 1 : stage + 2;
            load_slab(smem_u32, wstage, s + 2, i0, n0, tid);
        }

        const uint32_t stA = smem_u32 + stage * STAGE_BYTES;
        const uint32_t stB = stA + A_BYTES;

        #pragma unroll
        for (int kf = 0; kf < 4; kf++) {
            uint32_t a[2][4], b[4][4];
            #pragma unroll
            for (int p = 0; p < 2; p++) {
                int row = wm * 32 + p * 16 + (lid & 7) + ((lid >> 3) & 1) * 8;
                int ch  = 2 * kf + (lid >> 4);
                ldsm4(a[p], stA + chswz(row, ch));
            }
            #pragma unroll
            for (int p = 0; p < 4; p++) {
                int row = wn * 64 + p * 16 + (lid & 7) + (lid >> 4) * 8;
                int ch  = 2 * kf + ((lid >> 3) & 1);
                ldsm4(b[p], stB + chswz(row, ch));
            }
            #pragma unroll
            for (int mf = 0; mf < 2; mf++)
                #pragma unroll
                for (int nf = 0; nf < 8; nf++)
                    mma16816(acc[mf][nf], a[mf], &b[nf >> 1][(nf & 1) * 2]);
        }
        stage = (stage + 1 >= STAGES) ? 0 : stage + 1;
    }

    // epilogue: scatter compacted rows back to original token rows
    // (no barrier needed: accumulators are register-private, s_orig was
    //  written before the first loop barrier)
    const int g = lid >> 2, t = lid & 3;
    #pragma unroll
    for (int mf = 0; mf < 2; mf++) {
        const int r0 = wm * 32 + mf * 16 + g;
        const int o0 = s_orig[r0];
        const int o1 = s_orig[r0 + 8];
        #pragma unroll
        for (int nf = 0; nf < 8; nf++) {
            const int col = n0 + wn * 64 + nf * 8 + t * 2;
            if (o0 >= 0)
                *(float2*)&out[(size_t)o0 * N_DIM + col] =
                    make_float2(acc[mf][nf][0], acc[mf][nf][1]);
            if (o1 >= 0)
                *(float2*)&out[(size_t)o1 * N_DIM + col] =
                    make_float2(acc[mf][nf][2], acc[mf][nf][3]);
        }
    }
}

// ---------------- pre-pass kernels ----------------
__device__ __forceinline__ void cvt4_store(float4 x, __half* ph) {
    union { __half b[4]; uint2 u; } uh;
    uh.b[0] = __float2half(x.x); uh.b[1] = __float2half(x.y);
    uh.b[2] = __float2half(x.z); uh.b[3] = __float2half(x.w);
    *(uint2*)ph = uh.u;
}

__global__ void convert_w_kernel(const float* __restrict__ W) {
    if (blockIdx.x == 0 && threadIdx.x == 0) { g_count = 0; g_icount = 0; }
    const int n = blockIdx.x;
    const int k = threadIdx.x * 4;              // 288 threads cover K=1152
    const size_t o = (size_t)n * K_DIM + k;
    cvt4_store(*(const float4*)&W[o], g_Wh + o);
}

// assign compacted slots + invalid list + write amask / tok_item_ids
__global__ void compact_kernel(const int* __restrict__ ids, float* __restrict__ out) {
    int i = blockIdx.x * 256 + threadIdx.x;
    if (i >= TOKENS) return;
    int id = ids[i];
    bool valid = (id >= 0 && id < NUM_ITEMS_C);
    const size_t base = (size_t)TOKENS * N_DIM;
    out[base + i]          = valid ? 1.0f : 0.0f;
    out[base + TOKENS + i] = valid ? (float)id : -1.0f;
    if (valid) {
        int s = atomicAdd(&g_count, 1);
        g_slot[i] = s;
        g_c2o[s] = i;
    } else {
        g_slot[i] = -1;
        int s = atomicAdd(&g_icount, 1);
        g_inv[s] = i;
    }
}

// gather valid tokens into compacted rows, fp16
__global__ void gather_kernel(const int* __restrict__ ids,
                              const float* __restrict__ E,
                              const float* __restrict__ V) {
    const int i = blockIdx.x;
    const int slot = g_slot[i];
    if (slot < 0) return;
    const int k = threadIdx.x * 4;
    const int id = ids[i];
    float4 x = (k < D_SEM_DIM)
        ? *(const float4*)&E[(size_t)id * D_SEM_DIM + k]
        : *(const float4*)&V[(size_t)id * D_PROMPT_DIM + (k - D_SEM_DIM)];
    cvt4_store(x, g_Ah + (size_t)slot * K_DIM + k);
}

extern "C" void kernel_launch(void* const* d_in, const int* in_sizes, int n_in,
                              void* d_out, int out_size)
{
    const int*   ids      = (const int*)  d_in[0];
    const float* E_sem    = (const float*)d_in[2];
    const float* v_prompt = (const float*)d_in[3];
    const float* W        = (const float*)d_in[4];
    float*       out      = (float*)d_out;

    static bool attr_set = false;
    if (!attr_set) {
        cudaFuncSetAttribute(gemm_kernel, cudaFuncAttributeMaxDynamicSharedMemorySize, SMEM_TOTAL);
        attr_set = true;
    }

    convert_w_kernel<<<N_DIM, 288>>>(W);                         // also resets counters
    compact_kernel<<<(TOKENS + 255) / 256, 256>>>(ids, out);     // slots + inv list + amask/tok
    gather_kernel<<<TOKENS, 288>>>(ids, E_sem, v_prompt);        // compacted fp16 A
    dim3 grid(N_DIM / BN, TOKENS / BM + 1);                      // (16, 101)
    gemm_kernel<<<grid, NTHREADS, SMEM_TOTAL>>>(out);            // surplus tiles zero invalid rows
}

// round 17
// speedup vs baseline: 1.1272x; 1.0179x over previous
#include <cuda_runtime.h>
#include <cuda_fp16.h>
#include <cstdint>

// Single-term fp16 GEMM over compacted valid tokens; surplus GEMM CTAs
// zero the invalid output rows. 256 threads / 8 warps, 32x64 warp tiles,
// BN=128, 3-stage pipeline, 2 CTAs per SM, one barrier per K-slab.
// 3 launches: prep (W-convert || compact), gather (+counter recycle), gemm.
//
// Problem constants
#define TOKENS       12800
#define K_DIM        1152
#define D_SEM_DIM    768
#define D_PROMPT_DIM 384
#define N_DIM        2048
#define NUM_ITEMS_C  100000

// GEMM tiling
#define BM      128
#define BN      128
#define BK      64
#define NSLAB   (K_DIM / BK)               // 18
#define STAGES  3
#define NTHREADS 256

#define A_BYTES     (BM * BK * 2)          // 16384 (row stride 128 B)
#define B_BYTES     (BN * BK * 2)          // 16384
#define STAGE_BYTES (A_BYTES + B_BYTES)    // 32768
#define SMEM_TOTAL  (STAGES * STAGE_BYTES) // 98304 -> 2 CTAs/SM

// prep kernel grid split
#define PREP_W_BLOCKS   N_DIM                          // 2048
#define PREP_C_BLOCKS   ((TOKENS + 287) / 288)         // 45
#define PREP_THREADS    288

// fp16 operands: A gathered+compacted, W converted
__device__ __align__(256) __half g_Ah[(size_t)TOKENS * K_DIM];
__device__ __align__(256) __half g_Wh[(size_t)N_DIM * K_DIM];
// compaction state
__device__ int g_count;          // # valid tokens (reset by gather each call)
__device__ int g_icount;         // # invalid tokens
__device__ int g_ngemm;          // snapshot of g_count consumed by gemm
__device__ int g_slot[TOKENS];   // orig token -> compacted slot (-1 invalid)
__device__ int g_c2o[TOKENS];    // compacted slot -> orig token
__device__ int g_inv[TOKENS];    // invalid list -> orig token

// ---------------- helpers ----------------
__device__ __forceinline__ uint32_t smem_u32_of(const void* p) {
    uint32_t a;
    asm("{ .reg .u64 t; cvta.to.shared.u64 t, %1; cvt.u32.u64 %0, t; }" : "=r"(a) : "l"(p));
    return a;
}
__device__ __forceinline__ void cp16(uint32_t dst, const void* src) {
    asm volatile("cp.async.cg.shared.global [%0], [%1], 16;" :: "r"(dst), "l"(src) : "memory");
}
__device__ __forceinline__ void ldsm4(uint32_t* r, uint32_t addr) {
    asm volatile("ldmatrix.sync.aligned.m8n8.x4.shared.b16 {%0,%1,%2,%3}, [%4];"
                 : "=r"(r[0]), "=r"(r[1]), "=r"(r[2]), "=r"(r[3]) : "r"(addr));
}
__device__ __forceinline__ void mma16816(float* d, const uint32_t* a, const uint32_t* b) {
    asm volatile(
        "mma.sync.aligned.m16n8k16.row.col.f32.f16.f16.f32 "
        "{%0,%1,%2,%3}, {%4,%5,%6,%7}, {%8,%9}, {%0,%1,%2,%3};"
        : "+f"(d[0]), "+f"(d[1]), "+f"(d[2]), "+f"(d[3])
        : "r"(a[0]), "r"(a[1]), "r"(a[2]), "r"(a[3]), "r"(b[0]), "r"(b[1]));
}
// 128B-row swizzle: chunk' = c ^ (row & 7)
__device__ __forceinline__ uint32_t chswz(int row, int c) {
    return (uint32_t)(row * 128 + ((c ^ (row & 7)) << 4));
}

// load one K-slab (A 128x64, W 128x64 fp16) into a pipeline stage
__device__ __forceinline__ void load_slab(uint32_t smem_u32, int stage, int s,
                                          int i0, int n0, int tid) {
    const int kk = s * BK;
    const uint32_t stA = smem_u32 + stage * STAGE_BYTES;
    const uint32_t stB = stA + A_BYTES;
    #pragma unroll
    for (int i = 0; i < 4; i++) {                        // A: 1024 chunks of 16B
        int j = tid + NTHREADS * i, r = j >> 3, c = j & 7;
        cp16(stA + chswz(r, c), g_Ah + (size_t)(i0 + r) * K_DIM + kk + c * 8);
    }
    #pragma unroll
    for (int i = 0; i < 4; i++) {                        // W: 1024 chunks
        int j = tid + NTHREADS * i, r = j >> 3, c = j & 7;
        cp16(stB + chswz(r, c), g_Wh + (size_t)(n0 + r) * K_DIM + kk + c * 8);
    }
    asm volatile("cp.async.commit_group;" ::: "memory");
}

// ---------------- GEMM kernel (+ invalid-row zeroing on surplus tiles) ----
__global__ __launch_bounds__(NTHREADS, 2)
void gemm_kernel(float* __restrict__ out)
{
    const int n_valid  = g_ngemm;
    const int nv_tiles = (n_valid + BM - 1) / BM;
    const int tid = threadIdx.x;
    const int lid = tid & 31;
    const int wid = tid >> 5;
    const int n0  = blockIdx.x * BN;

    if ((int)blockIdx.y >= nv_tiles) {
        // surplus tile: zero invalid original rows for this BN column slice.
        const int yr = blockIdx.y - nv_tiles;
        const int n_invalid = TOKENS - n_valid;
        const float4 z = make_float4(0.f, 0.f, 0.f, 0.f);
        #pragma unroll
        for (int j = wid; j < BM; j += 8) {         // one warp per row
            int inv = yr * BM + j;
            if (inv < n_invalid) {
                float* p = out + (size_t)g_inv[inv] * N_DIM + n0 + lid * 4;
                *(float4*)p = z;                     // 32 lanes x 4 = 128 cols
            }
        }
        return;
    }

    const int i0 = blockIdx.y * BM;      // compacted-row tile start
    extern __shared__ char smem[];
    const uint32_t smem_u32 = smem_u32_of(smem);
    const int wm  = wid >> 1;            // 0..3 (32-row slab)
    const int wn  = wid & 1;             // 0..1 (64-col slab)

    __shared__ int s_orig[BM];
    if (tid < BM)
        s_orig[tid] = (i0 + tid < n_valid) ? g_c2o[i0 + tid] : -1;

    float acc[2][8][4];
    #pragma unroll
    for (int mf = 0; mf < 2; mf++)
        #pragma unroll
        for (int nf = 0; nf < 8; nf++)
            #pragma unroll
            for (int q = 0; q < 4; q++) acc[mf][nf][q] = 0.f;

    // prologue: stages 0..1
    load_slab(smem_u32, 0, 0, i0, n0, tid);
    load_slab(smem_u32, 1, 1, i0, n0, tid);

    int stage = 0;
    for (int s = 0; s < NSLAB; ++s) {
        // ensure group s landed (allow 1 newer pending)
        if (s < NSLAB - 1) asm volatile("cp.async.wait_group 1;" ::: "memory");
        else               asm volatile("cp.async.wait_group 0;" ::: "memory");
        // single barrier per slab: orders stage-s visibility and prior reads
        // of stage (s+2)%3 before we overwrite it below.
        __syncthreads();

        if (s + 2 < NSLAB) {
            int wstage = stage + 2 >= STAGES ? stage - 1 : stage + 2;
            load_slab(smem_u32, wstage, s + 2, i0, n0, tid);
        }

        const uint32_t stA = smem_u32 + stage * STAGE_BYTES;
        const uint32_t stB = stA + A_BYTES;

        #pragma unroll
        for (int kf = 0; kf < 4; kf++) {
            uint32_t a[2][4], b[4][4];
            #pragma unroll
            for (int p = 0; p < 2; p++) {
                int row = wm * 32 + p * 16 + (lid & 7) + ((lid >> 3) & 1) * 8;
                int ch  = 2 * kf + (lid >> 4);
                ldsm4(a[p], stA + chswz(row, ch));
            }
            #pragma unroll
            for (int p = 0; p < 4; p++) {
                int row = wn * 64 + p * 16 + (lid & 7) + (lid >> 4) * 8;
                int ch  = 2 * kf + ((lid >> 3) & 1);
                ldsm4(b[p], stB + chswz(row, ch));
            }
            #pragma unroll
            for (int mf = 0; mf < 2; mf++)
                #pragma unroll
                for (int nf = 0; nf < 8; nf++)
                    mma16816(acc[mf][nf], a[mf], &b[nf >> 1][(nf & 1) * 2]);
        }
        stage = (stage + 1 >= STAGES) ? 0 : stage + 1;
    }

    // epilogue: scatter compacted rows back to original token rows
    const int g = lid >> 2, t = lid & 3;
    #pragma unroll
    for (int mf = 0; mf < 2; mf++) {
        const int r0 = wm * 32 + mf * 16 + g;
        const int o0 = s_orig[r0];
        const int o1 = s_orig[r0 + 8];
        #pragma unroll
        for (int nf = 0; nf < 8; nf++) {
            const int col = n0 + wn * 64 + nf * 8 + t * 2;
            if (o0 >= 0)
                *(float2*)&out[(size_t)o0 * N_DIM + col] =
                    make_float2(acc[mf][nf][0], acc[mf][nf][1]);
            if (o1 >= 0)
                *(float2*)&out[(size_t)o1 * N_DIM + col] =
                    make_float2(acc[mf][nf][2], acc[mf][nf][3]);
        }
    }
}

// ---------------- pre-pass kernels ----------------
__device__ __forceinline__ void cvt4_store(float4 x, __half* ph) {
    union { __half b[4]; uint2 u; } uh;
    uh.b[0] = __float2half(x.x); uh.b[1] = __float2half(x.y);
    uh.b[2] = __float2half(x.z); uh.b[3] = __float2half(x.w);
    *(uint2*)ph = uh.u;
}

// fused prep: blocks [0, N_DIM) convert W to fp16; blocks [N_DIM, ...) run
// compaction (slots, invalid list, amask, tok_item_ids). Counters were
// zeroed by the previous call's gather_kernel (static-init zero on call 1).
__global__ void prep_kernel(const float* __restrict__ W,
                            const int* __restrict__ ids,
                            float* __restrict__ out) {
    if (blockIdx.x < PREP_W_BLOCKS) {
        const int n = blockIdx.x;
        const int k = threadIdx.x * 4;              // 288 threads cover K=1152
        const size_t o = (size_t)n * K_DIM + k;
        cvt4_store(*(const float4*)&W[o], g_Wh + o);
        return;
    }
    const int i = (blockIdx.x - PREP_W_BLOCKS) * PREP_THREADS + threadIdx.x;
    if (i >= TOKENS) return;
    int id = ids[i];
    bool valid = (id >= 0 && id < NUM_ITEMS_C);
    const size_t base = (size_t)TOKENS * N_DIM;
    out[base + i]          = valid ? 1.0f : 0.0f;
    out[base + TOKENS + i] = valid ? (float)id : -1.0f;
    if (valid) {
        int s = atomicAdd(&g_count, 1);
        g_slot[i] = s;
        g_c2o[s] = i;
    } else {
        g_slot[i] = -1;
        int s = atomicAdd(&g_icount, 1);
        g_inv[s] = i;
    }
}

// gather valid tokens into compacted rows, fp16.
// Block 0 thread 0 also snapshots g_count for the GEMM and zeroes the
// counters for the next graph replay (nothing else reads them this call).
__global__ void gather_kernel(const int* __restrict__ ids,
                              const float* __restrict__ E,
                              const float* __restrict__ V) {
    if (blockIdx.x == 0 && threadIdx.x == 0) {
        g_ngemm  = g_count;
        g_count  = 0;
        g_icount = 0;
    }
    const int i = blockIdx.x;
    const int slot = g_slot[i];
    if (slot < 0) return;
    const int k = threadIdx.x * 4;
    const int id = ids[i];
    float4 x = (k < D_SEM_DIM)
        ? *(const float4*)&E[(size_t)id * D_SEM_DIM + k]
        : *(const float4*)&V[(size_t)id * D_PROMPT_DIM + (k - D_SEM_DIM)];
    cvt4_store(x, g_Ah + (size_t)slot * K_DIM + k);
}

extern "C" void kernel_launch(void* const* d_in, const int* in_sizes, int n_in,
                              void* d_out, int out_size)
{
    const int*   ids      = (const int*)  d_in[0];
    const float* E_sem    = (const float*)d_in[2];
    const float* v_prompt = (const float*)d_in[3];
    const float* W        = (const float*)d_in[4];
    float*       out      = (float*)d_out;

    static bool attr_set = false;
    if (!attr_set) {
        cudaFuncSetAttribute(gemm_kernel, cudaFuncAttributeMaxDynamicSharedMemorySize, SMEM_TOTAL);
        attr_set = true;
    }

    prep_kernel<<<PREP_W_BLOCKS + PREP_C_BLOCKS, PREP_THREADS>>>(W, ids, out);
    gather_kernel<<<TOKENS, 288>>>(ids, E_sem, v_prompt);
    dim3 grid(N_DIM / BN, TOKENS / BM + 1);                      // (16, 101)
    gemm_kernel<<<grid, NTHREADS, SMEM_TOTAL>>>(out);
}